// round 11
// baseline (speedup 1.0000x reference)
#include <cuda_runtime.h>
#include <cuda_bf16.h>
#include <stdint.h>

// LSTM_3444563771996 : I=28, H=64, T=128, B=4096, OUT=10
// 2 CTAs/SM x 2 independent 4-warp groups (8 batch rows each, private named
// barrier, double-buffered h tile -> ONE barrier per step). Warp owns 16
// units x all 4 gates; activations fully in-register. bf16 hi/lo split
// mma.sync (3 terms), tanh.approx activations.

#define TI   128
#define II   28
#define HH   64
#define GG   256
#define BB   4096
#define OUTD 10
#define MB   16
#define NTHR 256

// ---- SMEM map (bytes) ----
// whh-hi region [0,36864) is dead after W_hh-hi fragments move to registers;
// overlaid by wih-hi/lo + Hs (exactly 36864).
#define SM_WHH_HI 0                 // [256][72] bf16 (init only)
#define SM_WIH_HI 0                 // overlay: [256][32] bf16 = 16384
#define SM_WIH_LO 16384             // 16384
#define SM_HS     32768             // fp32 h_T [16][64] = 4096
#define SM_WHH_LO 36864             // [256][72] bf16, live all kernel
#define SM_HB     73728             // h bufs [grp][buf][hi/lo][8][72]b16: 4608/grp
#define HB_G      4608
#define HB_B      2304
#define HB_P      1152
#define SM_XB     82944             // x bufs [grp][buf][hi/lo][8][32]b16: 2048/grp
#define XB_G      2048
#define XB_B      1024
#define XB_P      512
#define SMEM_BYTES 87040

typedef unsigned long long u64;

#define LDSM4(r, addr)                                                        \
    asm volatile("ldmatrix.sync.aligned.m8n8.x4.shared.b16 {%0,%1,%2,%3}, [%4];" \
                 : "=r"((r)[0]), "=r"((r)[1]), "=r"((r)[2]), "=r"((r)[3])     \
                 : "r"(addr))

#define MMA16816(d, a, b0_, b1_)                                              \
    asm volatile("mma.sync.aligned.m16n8k16.row.col.f32.bf16.bf16.f32 "       \
                 "{%0,%1,%2,%3}, {%4,%5,%6,%7}, {%8,%9}, {%0,%1,%2,%3};"      \
                 : "+f"((d)[0]), "+f"((d)[1]), "+f"((d)[2]), "+f"((d)[3])     \
                 : "r"((a)[0]), "r"((a)[1]), "r"((a)[2]), "r"((a)[3]),        \
                   "r"(b0_), "r"(b1_))

#define GBAR(id) asm volatile("bar.sync %0, %1;" :: "r"(id), "r"(128) : "memory")

static __device__ __forceinline__ uint32_t smem_u32(const void* p) {
    uint32_t a;
    asm("{ .reg .u64 t; cvta.to.shared.u64 t, %1; cvt.u32.u64 %0, t; }" : "=r"(a) : "l"(p));
    return a;
}
static __device__ __forceinline__ void split_bf16(float v, uint16_t& hi, uint16_t& lo) {
    __nv_bfloat16 h = __float2bfloat16_rn(v);
    __nv_bfloat16 l = __float2bfloat16_rn(v - __bfloat162float(h));
    hi = __bfloat16_as_ushort(h);
    lo = __bfloat16_as_ushort(l);
}
static __device__ __forceinline__ float tanhap(float v) {
    float r; asm("tanh.approx.f32 %0, %1;" : "=f"(r) : "f"(v)); return r;
}
static __device__ __forceinline__ float sigmap(float v) {
    return fmaf(0.5f, tanhap(0.5f * v), 0.5f);
}
static __device__ __forceinline__ void pack_x(const float4& xv, u64& ph, u64& pl) {
    uint16_t h0,l0,h1,l1,h2,l2,h3,l3;
    split_bf16(xv.x, h0, l0); split_bf16(xv.y, h1, l1);
    split_bf16(xv.z, h2, l2); split_bf16(xv.w, h3, l3);
    ph = (u64)h0 | ((u64)h1 << 16) | ((u64)h2 << 32) | ((u64)h3 << 48);
    pl = (u64)l0 | ((u64)l1 << 16) | ((u64)l2 << 32) | ((u64)l3 << 48);
}

__global__ __launch_bounds__(NTHR, 2)
void lstm_kernel(const float* __restrict__ x,
                 const float* __restrict__ W_ih, const float* __restrict__ W_hh,
                 const float* __restrict__ b_ih, const float* __restrict__ b_hh,
                 const float* __restrict__ W_out, const float* __restrict__ b_out,
                 float* __restrict__ out)
{
    extern __shared__ char smem[];
    const uint32_t sb = smem_u32(smem);
    const int tid  = threadIdx.x;
    const int lane = tid & 31;
    const int warp = tid >> 5;
    const int grp  = warp >> 2;          // 0/1: owns batch rows [grp*8, grp*8+8)
    const int wg   = warp & 3;           // units [16wg, 16wg+16), all 4 gates
    const int b0   = blockIdx.x * MB;

    // ---- init: zero everything, stage W_hh hi/lo (stride 72) ----
    for (int i = tid; i < SMEM_BYTES / 4; i += NTHR) ((uint32_t*)smem)[i] = 0u;
    __syncthreads();
    for (int idx = tid; idx < GG * HH; idx += NTHR) {
        int g = idx >> 6, k = idx & 63;
        uint16_t hi, lo; split_bf16(W_hh[g * HH + k], hi, lo);
        *(uint16_t*)(smem + SM_WHH_HI + (g * 72 + k) * 2) = hi;
        *(uint16_t*)(smem + SM_WHH_LO + (g * 72 + k) * 2) = lo;
    }
    __syncthreads();

    // ---- lane geometry ----
    const int l7 = lane & 7, lg = lane >> 3;
    const int arow = wg * 16 + l7 + ((lg & 1) << 3);   // A-frag row within gate block
    const int akh  = lg >> 1;                          // k8 half
    // whh-lo A-frag bases per gate type (stride 72 -> 144B rows)
    uint32_t whhLoA[4];
#pragma unroll
    for (int gt = 0; gt < 4; ++gt)
        whhLoA[gt] = sb + SM_WHH_LO + ((gt * 64 + arow) * 72 + akh * 8) * 2;

    // ---- cache W_hh-hi fragments in registers (4 gt x 4 kc x 4 = 64 regs) ----
    uint32_t whhR[4][4][4];
#pragma unroll
    for (int gt = 0; gt < 4; ++gt) {
        const uint32_t a0 = sb + SM_WHH_HI + ((gt * 64 + arow) * 72 + akh * 8) * 2;
#pragma unroll
        for (int kc = 0; kc < 4; ++kc) LDSM4(whhR[gt][kc], a0 + kc * 32);
    }
    __syncthreads();   // whh-hi region now dead

    // ---- overlay: zero + stage W_ih hi/lo (stride 32) ----
    for (int i = tid; i < 32768 / 4; i += NTHR) ((uint32_t*)smem)[i] = 0u;
    __syncthreads();
    for (int idx = tid; idx < GG * II; idx += NTHR) {
        int g = idx / II, k = idx - g * II;
        uint16_t hi, lo; split_bf16(W_ih[g * II + k], hi, lo);
        *(uint16_t*)(smem + SM_WIH_HI + (g * 32 + k) * 2) = hi;
        *(uint16_t*)(smem + SM_WIH_LO + (g * 32 + k) * 2) = lo;
    }
    // stage x(0)->buf0, x(1)->buf1 for both groups (rows 0..15)
    for (int idx = tid; idx < 2 * MB * 7; idx += NTHR) {
        int ts = idx / (MB * 7), rem = idx % (MB * 7);
        int row = rem / 7, seg = rem % 7;      // row 0..15 global-in-CTA
        const float4 xv = *reinterpret_cast<const float4*>(
            x + ((size_t)(b0 + row) * TI + ts) * II + seg * 4);
        u64 ph, pl; pack_x(xv, ph, pl);
        const int g2 = row >> 3, lr = row & 7;
        uint32_t base = SM_XB + g2 * XB_G + ts * XB_B + (lr * 32 + seg * 4) * 2;
        *(u64*)(smem + base)        = ph;
        *(u64*)(smem + base + XB_P) = pl;
    }

    // wih A-frag bases (stride 32 -> 64B rows)
    uint32_t wihHiA[4], wihLoA[4];
#pragma unroll
    for (int gt = 0; gt < 4; ++gt) {
        wihHiA[gt] = sb + SM_WIH_HI + ((gt * 64 + arow) * 32 + akh * 8) * 2;
        wihLoA[gt] = sb + SM_WIH_LO + ((gt * 64 + arow) * 32 + akh * 8) * 2;
    }
    // B-frag bases: k32-span LDSM4, lane addr = row(l7) , ktile(lg)
    const uint32_t hB = sb + SM_HB + grp * HB_G + l7 * 144 + lg * 16;
    const uint32_t xB = sb + SM_XB + grp * XB_G + l7 * 64 + lg * 16;

    // per-thread cell constants: units u0 = 16wg + (lane>>2), u0+8
    const int grow = lane >> 2;
    const int bcol = (lane & 3) * 2;
    const int u0 = wg * 16 + grow;
    float bias[4][2];                      // [gate][unit half]
#pragma unroll
    for (int gt = 0; gt < 4; ++gt) {
        bias[gt][0] = b_ih[gt * 64 + u0]     + b_hh[gt * 64 + u0];
        bias[gt][1] = b_ih[gt * 64 + u0 + 8] + b_hh[gt * 64 + u0 + 8];
    }
    float c[4] = {0.f, 0.f, 0.f, 0.f};     // (u0,b0),(u0,b1),(u0+8,b0),(u0+8,b1)

    // x prefetch: 56 threads per group own (local row, seg)
    const int gtid = tid & 127;
    const bool stager = gtid < 56;
    const int slr = gtid / 7, sseg = gtid % 7;
    float4 xreg;
    if (stager)
        xreg = *reinterpret_cast<const float4*>(
            x + ((size_t)(b0 + grp * 8 + slr) * TI + 2) * II + sseg * 4);

    __syncthreads();

    float acc[4][4];                       // [gate][frag]
    auto acc_init = [&]() {
#pragma unroll
        for (int gt = 0; gt < 4; ++gt) {
            acc[gt][0] = bias[gt][0]; acc[gt][1] = bias[gt][0];
            acc[gt][2] = bias[gt][1]; acc[gt][3] = bias[gt][1];
        }
    };
    auto xw_accum = [&](int buf) {
        uint32_t bh[4], bl[4];
        LDSM4(bh, xB + buf * XB_B);
        LDSM4(bl, xB + buf * XB_B + XB_P);
#pragma unroll
        for (int gt = 0; gt < 4; ++gt)
#pragma unroll
            for (int kc = 0; kc < 2; ++kc) {
                uint32_t wh[4], wl[4];
                LDSM4(wh, wihHiA[gt] + kc * 32);
                LDSM4(wl, wihLoA[gt] + kc * 32);
                MMA16816(acc[gt], wh, bh[2*kc], bh[2*kc+1]);
                MMA16816(acc[gt], wh, bl[2*kc], bl[2*kc+1]);
                MMA16816(acc[gt], wl, bh[2*kc], bh[2*kc+1]);
            }
    };

    acc_init();
    xw_accum(0);                           // xw(0)

    const int barid = 1 + grp;
    for (int t = 0; t < TI; ++t) {
        const int p = t & 1;
        // ---- h-GEMM: acc += W_hh * h(t-1) from hbuf[p] ----
        uint32_t bh0[4], bh1[4], bl0[4], bl1[4];
        LDSM4(bh0, hB + p * HB_B);          // k 0..31, hi
        LDSM4(bh1, hB + p * HB_B + 64);     // k 32..63, hi
        LDSM4(bl0, hB + p * HB_B + HB_P);
        LDSM4(bl1, hB + p * HB_B + HB_P + 64);
#pragma unroll
        for (int gt = 0; gt < 4; ++gt) {
#pragma unroll
            for (int kc = 0; kc < 4; ++kc) {
                uint32_t wl[4];
                LDSM4(wl, whhLoA[gt] + kc * 32);
                const uint32_t* bhk = (kc < 2) ? bh0 : bh1;
                const uint32_t* blk = (kc < 2) ? bl0 : bl1;
                const int q = (kc & 1) * 2;
                MMA16816(acc[gt], whhR[gt][kc], bhk[q], bhk[q+1]);
                MMA16816(acc[gt], whhR[gt][kc], blk[q], blk[q+1]);
                MMA16816(acc[gt], wl,           bhk[q], bhk[q+1]);
            }
        }

        // ---- in-register activations; h -> hbuf[1-p] ----
#pragma unroll
        for (int e = 0; e < 4; ++e) {
            float ig = sigmap(acc[0][e]);
            float fg = sigmap(acc[1][e]);
            float gg = tanhap(acc[2][e]);
            float og = sigmap(acc[3][e]);
            float cv = fmaf(fg, c[e], ig * gg);
            c[e] = cv;
            float hv = og * tanhap(cv);
            uint16_t hh16, hl16; split_bf16(hv, hh16, hl16);
            const int cb = bcol + (e & 1);             // local batch row
            const int uu = u0 + (e >> 1) * 8;          // unit
            uint32_t hadr = SM_HB + grp * HB_G + (1 - p) * HB_B + (cb * 72 + uu) * 2;
            *(uint16_t*)(smem + hadr)        = hh16;
            *(uint16_t*)(smem + hadr + HB_P) = hl16;
            if (t == TI - 1)
                ((float*)(smem + SM_HS))[(grp * 8 + cb) * HH + uu] = hv;
        }
        // ---- stage x(t+2) from regs; refill x(t+3) ----
        if (stager && t + 2 < TI) {
            u64 ph, pl; pack_x(xreg, ph, pl);
            uint32_t base = SM_XB + grp * XB_G + p * XB_B + (slr * 32 + sseg * 4) * 2;
            *(u64*)(smem + base)        = ph;
            *(u64*)(smem + base + XB_P) = pl;
            if (t + 3 < TI)
                xreg = *reinterpret_cast<const float4*>(
                    x + ((size_t)(b0 + grp * 8 + slr) * TI + (t + 3)) * II + sseg * 4);
        }
        // ---- acc = bias + xw(t+1) (off h-path) ----
        if (t + 1 < TI) {
            acc_init();
            xw_accum((t + 1) & 1);
        }
        GBAR(barid);   // orders: h STS before next reads; x stage before xw(t+2)
    }

    // ---- final linear: out = h_T @ W_out^T + b_out ----
    __syncthreads();
    float* scr = (float*)(smem + SM_HB);   // h bufs dead now
    for (int idx = tid; idx < OUTD * HH; idx += NTHR) scr[idx] = W_out[idx];
    if (tid < OUTD) scr[OUTD * HH + tid] = b_out[tid];
    __syncthreads();

    const float* Hs = (const float*)(smem + SM_HS);
    for (int cell = tid; cell < MB * OUTD; cell += NTHR) {
        int row = cell / OUTD;
        int o   = cell - row * OUTD;
        float s = scr[OUTD * HH + o];
#pragma unroll
        for (int j = 0; j < HH; ++j)
            s = fmaf(Hs[row * HH + j], scr[o * HH + j], s);
        out[(size_t)(b0 + row) * OUTD + o] = s;
    }
}

extern "C" void kernel_launch(void* const* d_in, const int* in_sizes, int n_in,
                              void* d_out, int out_size)
{
    const float* x     = (const float*)d_in[0];
    const float* W_ih  = (const float*)d_in[1];
    const float* W_hh  = (const float*)d_in[2];
    const float* b_ih  = (const float*)d_in[3];
    const float* b_hh  = (const float*)d_in[4];
    const float* W_out = (const float*)d_in[5];
    const float* b_out = (const float*)d_in[6];
    float* outp = (float*)d_out;

    cudaFuncSetAttribute(lstm_kernel,
                         cudaFuncAttributeMaxDynamicSharedMemorySize, SMEM_BYTES);
    lstm_kernel<<<BB / MB, NTHR, SMEM_BYTES>>>(x, W_ih, W_hh, b_ih, b_hh,
                                               W_out, b_out, outp);
}

// round 12
// speedup vs baseline: 2.2006x; 2.2006x over previous
#include <cuda_runtime.h>
#include <cuda_bf16.h>
#include <stdint.h>

// LSTM_3444563771996 : I=28, H=64, T=128, B=4096, OUT=10
// R10 structure (warp = 8 units x 16 batch, in-register activations,
// W_hh fragments register-cached, 2 CTAs/SM) + double-buffered h tile
// -> ONE __syncthreads per timestep.
// bf16 hi/lo split mma.sync (3 terms), tanh.approx activations.

#define TI   128
#define II   28
#define HH   64
#define GG   256
#define BB   4096
#define OUTD 10
#define MB   16
#define NTHR 256

#define WST  72     // whh/h tiles: 144B rows
#define XSTR 40     // wih/x tiles: 80B rows

// ---- SMEM map (bytes). whh staging dead after init -> overlaid. ----
#define SM_WHH_HI 0                    // [256][72] bf16 = 36864 (init only)
#define SM_WHH_LO 36864                // .. 73728 (init only; frags cached)
#define SM_WIH_HI 0                    // overlay: [256][40] = 20480
#define SM_WIH_LO 20480                // .. 40960
#define SM_SCR    40960                // epilogue scratch
#define SM_H      73728                // [buf][hi,lo][16][72]b16 ; per buf 4608
#define HB_B      4608
#define HB_P      2304
#define SM_X      82944                // 2 bufs x (hi 1280 + lo 1280)
#define XBUF      2560
#define SMEM_BYTES 88064

typedef unsigned long long u64;

#define LDSM4(r, addr)                                                        \
    asm volatile("ldmatrix.sync.aligned.m8n8.x4.shared.b16 {%0,%1,%2,%3}, [%4];" \
                 : "=r"((r)[0]), "=r"((r)[1]), "=r"((r)[2]), "=r"((r)[3])     \
                 : "r"(addr))

#define MMA16816(d, a, b0_, b1_)                                              \
    asm volatile("mma.sync.aligned.m16n8k16.row.col.f32.bf16.bf16.f32 "       \
                 "{%0,%1,%2,%3}, {%4,%5,%6,%7}, {%8,%9}, {%0,%1,%2,%3};"      \
                 : "+f"((d)[0]), "+f"((d)[1]), "+f"((d)[2]), "+f"((d)[3])     \
                 : "r"((a)[0]), "r"((a)[1]), "r"((a)[2]), "r"((a)[3]),        \
                   "r"(b0_), "r"(b1_))

static __device__ __forceinline__ uint32_t smem_u32(const void* p) {
    uint32_t a;
    asm("{ .reg .u64 t; cvta.to.shared.u64 t, %1; cvt.u32.u64 %0, t; }" : "=r"(a) : "l"(p));
    return a;
}
static __device__ __forceinline__ void split_bf16(float v, uint16_t& hi, uint16_t& lo) {
    __nv_bfloat16 h = __float2bfloat16_rn(v);
    __nv_bfloat16 l = __float2bfloat16_rn(v - __bfloat162float(h));
    hi = __bfloat16_as_ushort(h);
    lo = __bfloat16_as_ushort(l);
}
static __device__ __forceinline__ float tanhap(float v) {
    float r; asm("tanh.approx.f32 %0, %1;" : "=f"(r) : "f"(v)); return r;
}
static __device__ __forceinline__ float sigmap(float v) {
    return fmaf(0.5f, tanhap(0.5f * v), 0.5f);
}
static __device__ __forceinline__ void pack_x(const float4& xv, u64& ph, u64& pl) {
    uint16_t h0,l0,h1,l1,h2,l2,h3,l3;
    split_bf16(xv.x, h0, l0); split_bf16(xv.y, h1, l1);
    split_bf16(xv.z, h2, l2); split_bf16(xv.w, h3, l3);
    ph = (u64)h0 | ((u64)h1 << 16) | ((u64)h2 << 32) | ((u64)h3 << 48);
    pl = (u64)l0 | ((u64)l1 << 16) | ((u64)l2 << 32) | ((u64)l3 << 48);
}

__global__ __launch_bounds__(NTHR, 2)
void lstm_kernel(const float* __restrict__ x,
                 const float* __restrict__ W_ih, const float* __restrict__ W_hh,
                 const float* __restrict__ b_ih, const float* __restrict__ b_hh,
                 const float* __restrict__ W_out, const float* __restrict__ b_out,
                 float* __restrict__ out)
{
    extern __shared__ char smem[];
    const uint32_t sb = smem_u32(smem);
    const int tid  = threadIdx.x;
    const int lane = tid & 31;
    const int warp = tid >> 5;          // 0..7 -> units [8w, 8w+8)
    const int us   = warp * 8;
    const int b0   = blockIdx.x * MB;

    // ---- phase 0: zero h/x tiles; stage W_hh hi/lo ----
    for (int i = tid; i < (SMEM_BYTES - SM_H) / 4; i += NTHR)
        ((uint32_t*)(smem + SM_H))[i] = 0u;
    for (int idx = tid; idx < GG * HH; idx += NTHR) {
        int g = idx >> 6, k = idx & 63;
        uint16_t hi, lo; split_bf16(W_hh[g * HH + k], hi, lo);
        *(uint16_t*)(smem + SM_WHH_HI + (g * WST + k) * 2) = hi;
        *(uint16_t*)(smem + SM_WHH_LO + (g * WST + k) * 2) = lo;
    }
    __syncthreads();

    // ---- lane geometry ----
    const int l7 = lane & 7, lg = lane >> 3;
    const int rIF = ((lg & 1) ? 64 : 0) + us + l7;   // i/f gate rows
    const int rGO = rIF + 128;                       // g/o gate rows
    const uint32_t cof = (uint32_t)((lg >> 1) * 16); // k8 half (bytes)
    const int brow = l7 + ((lg >> 1) << 3);          // batch rows (B-frag)
    const uint32_t bko = (uint32_t)((lg & 1) * 16);

    // ---- phase 1: cache all W_hh fragments in registers; stage x(0),x(1) ----
    uint32_t whhIF[4][2][4], whhGO[4][2][4];   // [kc][hi/lo][4]
    {
        const uint32_t aIFh = sb + SM_WHH_HI + (uint32_t)rIF * 144 + cof;
        const uint32_t aIFl = sb + SM_WHH_LO + (uint32_t)rIF * 144 + cof;
        const uint32_t aGOh = sb + SM_WHH_HI + (uint32_t)rGO * 144 + cof;
        const uint32_t aGOl = sb + SM_WHH_LO + (uint32_t)rGO * 144 + cof;
#pragma unroll
        for (int kc = 0; kc < 4; ++kc) {
            LDSM4(whhIF[kc][0], aIFh + kc * 32);
            LDSM4(whhIF[kc][1], aIFl + kc * 32);
            LDSM4(whhGO[kc][0], aGOh + kc * 32);
            LDSM4(whhGO[kc][1], aGOl + kc * 32);
        }
    }
    for (int idx = tid; idx < 2 * MB * 7; idx += NTHR) {
        int ts = idx / (MB * 7), rem = idx % (MB * 7);
        int row = rem / 7, seg = rem % 7;
        const float4 xv = *reinterpret_cast<const float4*>(
            x + ((size_t)(b0 + row) * TI + ts) * II + seg * 4);
        u64 ph, pl; pack_x(xv, ph, pl);
        *(u64*)(smem + SM_X + ts * XBUF + (row * XSTR + seg * 4) * 2)        = ph;
        *(u64*)(smem + SM_X + ts * XBUF + 1280 + (row * XSTR + seg * 4) * 2) = pl;
    }
    __syncthreads();

    // ---- phase 2: zero wih overlay region ----
    for (int i = tid; i < 40960 / 4; i += NTHR) ((uint32_t*)smem)[i] = 0u;
    __syncthreads();

    // ---- phase 3: stage W_ih hi/lo ----
    for (int idx = tid; idx < GG * II; idx += NTHR) {
        int g = idx / II, k = idx - g * II;
        uint16_t hi, lo; split_bf16(W_ih[g * II + k], hi, lo);
        *(uint16_t*)(smem + SM_WIH_HI + (g * XSTR + k) * 2) = hi;
        *(uint16_t*)(smem + SM_WIH_LO + (g * XSTR + k) * 2) = lo;
    }

    // per-thread cell constants
    const int grow = lane >> 2;
    const int bcol = (lane & 3) * 2;
    const int u    = us + grow;
    const float bI = b_ih[u]       + b_hh[u];
    const float bF = b_ih[u + 64]  + b_hh[u + 64];
    const float bG = b_ih[u + 128] + b_hh[u + 128];
    const float bO = b_ih[u + 192] + b_hh[u + 192];
    float c[4] = {0.f, 0.f, 0.f, 0.f};

    // address bases
    const uint32_t xIFh = sb + SM_WIH_HI + (uint32_t)rIF * 80 + cof;
    const uint32_t xIFl = sb + SM_WIH_LO + (uint32_t)rIF * 80 + cof;
    const uint32_t xGOh = sb + SM_WIH_HI + (uint32_t)rGO * 80 + cof;
    const uint32_t xGOl = sb + SM_WIH_LO + (uint32_t)rGO * 80 + cof;
    const uint32_t hBF  = sb + SM_H + (uint32_t)brow * 144 + bko;  // + buf*HB_B (+HB_P lo)
    const uint32_t bxo  = (uint32_t)brow * 80 + bko;

    // x prefetch: threads < 112 each own (row, seg)
    const bool stager = tid < MB * 7;
    const int srow = tid / 7, sseg = tid % 7;
    float4 xreg;
    if (stager)
        xreg = *reinterpret_cast<const float4*>(
            x + ((size_t)(b0 + srow) * TI + 2) * II + sseg * 4);

    __syncthreads();

    float accIF[2][4], accGO[2][4];
    auto xw_compute = [&](int buf) {
#pragma unroll
        for (int j = 0; j < 2; ++j) {
            accIF[j][0] = bI; accIF[j][1] = bI; accIF[j][2] = bF; accIF[j][3] = bF;
            accGO[j][0] = bG; accGO[j][1] = bG; accGO[j][2] = bO; accGO[j][3] = bO;
        }
        const uint32_t xh = sb + SM_X + buf * XBUF + bxo;
        const uint32_t xl = xh + 1280;
#pragma unroll
        for (int kc = 0; kc < 2; ++kc) {
            uint32_t wIFh[4], wIFl[4], wGOh[4], wGOl[4], bh[4], bl[4];
            LDSM4(wIFh, xIFh + kc * 32);
            LDSM4(wIFl, xIFl + kc * 32);
            LDSM4(wGOh, xGOh + kc * 32);
            LDSM4(wGOl, xGOl + kc * 32);
            LDSM4(bh, xh + kc * 32);
            LDSM4(bl, xl + kc * 32);
#pragma unroll
            for (int j = 0; j < 2; ++j) {
                MMA16816(accIF[j], wIFh, bh[2*j], bh[2*j+1]);
                MMA16816(accIF[j], wIFh, bl[2*j], bl[2*j+1]);
                MMA16816(accIF[j], wIFl, bh[2*j], bh[2*j+1]);
                MMA16816(accGO[j], wGOh, bh[2*j], bh[2*j+1]);
                MMA16816(accGO[j], wGOh, bl[2*j], bl[2*j+1]);
                MMA16816(accGO[j], wGOl, bh[2*j], bh[2*j+1]);
            }
        }
    };
    xw_compute(0);

    for (int t = 0; t < TI; ++t) {
        const int p = t & 1;
        // ---- h-GEMM: acc += W_hh * h(t-1) from hbuf[p] ----
        const uint32_t bh_hi = hBF + p * HB_B;
        const uint32_t bh_lo = bh_hi + HB_P;
#pragma unroll
        for (int kc = 0; kc < 4; ++kc) {
            uint32_t bh[4], bl[4];
            LDSM4(bh, bh_hi + kc * 32);
            LDSM4(bl, bh_lo + kc * 32);
#pragma unroll
            for (int j = 0; j < 2; ++j) {
                MMA16816(accIF[j], whhIF[kc][0], bh[2*j], bh[2*j+1]);
                MMA16816(accIF[j], whhIF[kc][0], bl[2*j], bl[2*j+1]);
                MMA16816(accIF[j], whhIF[kc][1], bh[2*j], bh[2*j+1]);
                MMA16816(accGO[j], whhGO[kc][0], bh[2*j], bh[2*j+1]);
                MMA16816(accGO[j], whhGO[kc][0], bl[2*j], bl[2*j+1]);
                MMA16816(accGO[j], whhGO[kc][1], bh[2*j], bh[2*j+1]);
            }
        }

        // ---- in-register activations; h(t) -> hbuf[1-p] (no WAR: other buf) ----
        const uint32_t hw_hi = SM_H + (1 - p) * HB_B;
#pragma unroll
        for (int j = 0; j < 2; ++j)
#pragma unroll
            for (int e = 0; e < 2; ++e) {
                float ig = sigmap(accIF[j][e]);
                float fg = sigmap(accIF[j][2 + e]);
                float gg = tanhap(accGO[j][e]);
                float og = sigmap(accGO[j][2 + e]);
                float cv = fmaf(fg, c[j * 2 + e], ig * gg);
                c[j * 2 + e] = cv;
                float hv = og * tanhap(cv);
                uint16_t hh16, hl16; split_bf16(hv, hh16, hl16);
                const int cb = j * 8 + bcol + e;
                *(uint16_t*)(smem + hw_hi + (cb * WST + u) * 2)        = hh16;
                *(uint16_t*)(smem + hw_hi + HB_P + (cb * WST + u) * 2) = hl16;
            }
        // ---- stage x(t+2) from regs; refill with x(t+3) ----
        if (stager && t + 2 < TI) {
            u64 ph, pl; pack_x(xreg, ph, pl);
            *(u64*)(smem + SM_X + p * XBUF + (srow * XSTR + sseg * 4) * 2)        = ph;
            *(u64*)(smem + SM_X + p * XBUF + 1280 + (srow * XSTR + sseg * 4) * 2) = pl;
            if (t + 3 < TI)
                xreg = *reinterpret_cast<const float4*>(
                    x + ((size_t)(b0 + srow) * TI + (t + 3)) * II + sseg * 4);
        }
        // ---- acc = bias + xw(t+1) (reads xbuf[(t+1)&1], disjoint from stage) ----
        if (t + 1 < TI) xw_compute((t + 1) & 1);

        __syncthreads();   // publishes h(t) + x(t+2) for next iteration
    }

    // ---- final linear: out = h_T @ W_out^T + b_out ----
    // last h stored to buf[1 - (127&1)] = buf0
    float* scr = (float*)(smem + SM_SCR);
    for (int idx = tid; idx < OUTD * HH; idx += NTHR) scr[idx] = W_out[idx];
    if (tid < OUTD) scr[OUTD * HH + tid] = b_out[tid];
    __syncthreads();

    const __nv_bfloat16* hhp = (const __nv_bfloat16*)(smem + SM_H);
    const __nv_bfloat16* hlp = (const __nv_bfloat16*)(smem + SM_H + HB_P);
    for (int cell = tid; cell < MB * OUTD; cell += NTHR) {
        int row = cell / OUTD;
        int o   = cell - row * OUTD;
        float s = scr[OUTD * HH + o];
#pragma unroll
        for (int j = 0; j < HH; ++j) {
            float hv = __bfloat162float(hhp[row * WST + j]) +
                       __bfloat162float(hlp[row * WST + j]);
            s = fmaf(hv, scr[o * HH + j], s);
        }
        out[(size_t)(b0 + row) * OUTD + o] = s;
    }
}

extern "C" void kernel_launch(void* const* d_in, const int* in_sizes, int n_in,
                              void* d_out, int out_size)
{
    const float* x     = (const float*)d_in[0];
    const float* W_ih  = (const float*)d_in[1];
    const float* W_hh  = (const float*)d_in[2];
    const float* b_ih  = (const float*)d_in[3];
    const float* b_hh  = (const float*)d_in[4];
    const float* W_out = (const float*)d_in[5];
    const float* b_out = (const float*)d_in[6];
    float* outp = (float*)d_out;

    cudaFuncSetAttribute(lstm_kernel,
                         cudaFuncAttributeMaxDynamicSharedMemorySize, SMEM_BYTES);
    lstm_kernel<<<BB / MB, NTHR, SMEM_BYTES>>>(x, W_ih, W_hh, b_ih, b_hh,
                                               W_out, b_out, outp);
}

// round 16
// speedup vs baseline: 2.7221x; 1.2370x over previous
#include <cuda_runtime.h>
#include <cuda_bf16.h>
#include <stdint.h>

// LSTM_3444563771996 : I=28, H=64, T=128, B=4096, OUT=10
// R12 structure (warp = 8 units x 16 batch [i;f]/[g;o] m16 tiles, in-register
// activations, double-buffered h, ONE barrier/step, 2 CTAs/SM) with the GEMM
// switched to tf32 mma.sync.m16n8k8: 48 MMAs/warp/step vs 72 (no hi/lo split).
// W_hh fragments register-cached; h/x stored as tf32-rounded fp32.

#define TI   128
#define II   28
#define HH   64
#define GG   256
#define BB   4096
#define OUTD 10
#define MB   16
#define NTHR 256

#define WKS  68     // W_hh / h row stride (floats): bank = 4*gq+tig -> conflict-free
#define XKS  36     // W_ih / x row stride (floats)

// ---- SMEM map (bytes). W_hh staging [0,69632) dead after frag caching. ----
#define SM_WHH  0                    // [256][68] fp32 = 69632 (init only)
#define SM_WIH  0                    // overlay: [256][36] fp32 = 36864
#define SM_HS   36864                // fp32 h_T [16][64] = 4096
#define SM_SCR  40960                // epilogue scratch
#define SM_H    69632                // h bufs [2][16][68] fp32, 4352/buf
#define HB      4352
#define SM_X    78336                // x bufs [2][16][36] fp32, 2304/buf
#define XB      2304
#define SMEM_BYTES 82944

#define MMAT(d, a, b0_, b1_)                                                  \
    asm volatile("mma.sync.aligned.m16n8k8.row.col.f32.tf32.tf32.f32 "        \
                 "{%0,%1,%2,%3}, {%4,%5,%6,%7}, {%8,%9}, {%0,%1,%2,%3};"      \
                 : "+f"((d)[0]), "+f"((d)[1]), "+f"((d)[2]), "+f"((d)[3])     \
                 : "r"((a)[0]), "r"((a)[1]), "r"((a)[2]), "r"((a)[3]),        \
                   "r"(b0_), "r"(b1_))

static __device__ __forceinline__ uint32_t tf32_(float v) {
    uint32_t r; asm("cvt.rna.tf32.f32 %0, %1;" : "=r"(r) : "f"(v)); return r;
}
static __device__ __forceinline__ float tanhap(float v) {
    float r; asm("tanh.approx.f32 %0, %1;" : "=f"(r) : "f"(v)); return r;
}
static __device__ __forceinline__ float sigmap(float v) {
    return fmaf(0.5f, tanhap(0.5f * v), 0.5f);
}

__global__ __launch_bounds__(NTHR, 2)
void lstm_kernel(const float* __restrict__ x,
                 const float* __restrict__ W_ih, const float* __restrict__ W_hh,
                 const float* __restrict__ b_ih, const float* __restrict__ b_hh,
                 const float* __restrict__ W_out, const float* __restrict__ b_out,
                 float* __restrict__ out)
{
    extern __shared__ char smem[];
    uint32_t* smw = (uint32_t*)smem;
    const int tid  = threadIdx.x;
    const int lane = tid & 31;
    const int warp = tid >> 5;          // 0..7 -> units [8w, 8w+8)
    const int us   = warp * 8;
    const int b0   = blockIdx.x * MB;

    // ---- init: zero all, stage W_hh (tf32-rounded) + x(0),x(1) ----
    for (int i = tid; i < SMEM_BYTES / 4; i += NTHR) smw[i] = 0u;
    __syncthreads();
    for (int idx = tid; idx < GG * HH; idx += NTHR) {
        int g = idx >> 6, k = idx & 63;
        smw[g * WKS + k] = tf32_(W_hh[g * HH + k]);
    }
    for (int idx = tid; idx < 2 * MB * 7; idx += NTHR) {
        int ts = idx / (MB * 7), rem = idx % (MB * 7);
        int row = rem / 7, seg = rem % 7;
        const float4 xv = *reinterpret_cast<const float4*>(
            x + ((size_t)(b0 + row) * TI + ts) * II + seg * 4);
        uint4 q = make_uint4(tf32_(xv.x), tf32_(xv.y), tf32_(xv.z), tf32_(xv.w));
        *(uint4*)(smem + SM_X + ts * XB + (row * XKS + seg * 4) * 4) = q;
    }
    __syncthreads();

    // ---- lane geometry (tf32 m16n8k8 fragments) ----
    const int gq  = lane >> 2;          // groupID
    const int tig = lane & 3;           // thread in group

    // ---- cache W_hh A-fragments in registers (64 regs) ----
    uint32_t whhIF[8][4], whhGO[8][4];
    {
        const int rI = (us + gq) * WKS + tig;          // i rows
        const int rF = (64 + us + gq) * WKS + tig;     // f rows
        const int rG = (128 + us + gq) * WKS + tig;    // g rows
        const int rO = (192 + us + gq) * WKS + tig;    // o rows
#pragma unroll
        for (int kc = 0; kc < 8; ++kc) {
            whhIF[kc][0] = smw[rI + kc * 8];
            whhIF[kc][1] = smw[rF + kc * 8];
            whhIF[kc][2] = smw[rI + kc * 8 + 4];
            whhIF[kc][3] = smw[rF + kc * 8 + 4];
            whhGO[kc][0] = smw[rG + kc * 8];
            whhGO[kc][1] = smw[rO + kc * 8];
            whhGO[kc][2] = smw[rG + kc * 8 + 4];
            whhGO[kc][3] = smw[rO + kc * 8 + 4];
        }
    }
    __syncthreads();   // W_hh region dead

    // ---- overlay: zero + stage W_ih (tf32-rounded) ----
    for (int i = tid; i < SM_SCR / 4; i += NTHR) smw[i] = 0u;
    __syncthreads();
    for (int idx = tid; idx < GG * II; idx += NTHR) {
        int g = idx / II, k = idx - g * II;
        smw[g * XKS + k] = tf32_(W_ih[g * II + k]);
    }

    // per-thread cell constants
    const int u = us + gq;
    const float bI = b_ih[u]       + b_hh[u];
    const float bF = b_ih[u + 64]  + b_hh[u + 64];
    const float bG = b_ih[u + 128] + b_hh[u + 128];
    const float bO = b_ih[u + 192] + b_hh[u + 192];
    float c[4] = {0.f, 0.f, 0.f, 0.f};

    // fragment index bases
    const int wI = (us + gq) * XKS + tig;
    const int wF = (64 + us + gq) * XKS + tig;
    const int wG = (128 + us + gq) * XKS + tig;
    const int wO = (192 + us + gq) * XKS + tig;
    const int hb0 = gq * WKS + tig;            // batch 0..7 B-frags
    const int hb1 = (8 + gq) * WKS + tig;      // batch 8..15
    const int xb0 = gq * XKS + tig;
    const int xb1 = (8 + gq) * XKS + tig;

    // x prefetch: threads < 112 own (row, seg)
    const bool stager = tid < MB * 7;
    const int srow = tid / 7, sseg = tid % 7;
    float4 xreg;
    if (stager)
        xreg = *reinterpret_cast<const float4*>(
            x + ((size_t)(b0 + srow) * TI + 2) * II + sseg * 4);

    __syncthreads();

    float accIF[2][4], accGO[2][4];
    auto xw_compute = [&](int buf) {
#pragma unroll
        for (int j = 0; j < 2; ++j) {
            accIF[j][0] = bI; accIF[j][1] = bI; accIF[j][2] = bF; accIF[j][3] = bF;
            accGO[j][0] = bG; accGO[j][1] = bG; accGO[j][2] = bO; accGO[j][3] = bO;
        }
        const uint32_t* xs = (const uint32_t*)(smem + SM_X + buf * XB);
#pragma unroll
        for (int kc = 0; kc < 4; ++kc) {
            uint32_t aIF[4], aGO[4];
            aIF[0] = smw[wI + kc * 8];     aIF[1] = smw[wF + kc * 8];
            aIF[2] = smw[wI + kc * 8 + 4]; aIF[3] = smw[wF + kc * 8 + 4];
            aGO[0] = smw[wG + kc * 8];     aGO[1] = smw[wO + kc * 8];
            aGO[2] = smw[wG + kc * 8 + 4]; aGO[3] = smw[wO + kc * 8 + 4];
            uint32_t b00 = xs[xb0 + kc * 8], b01 = xs[xb0 + kc * 8 + 4];
            uint32_t b10 = xs[xb1 + kc * 8], b11 = xs[xb1 + kc * 8 + 4];
            MMAT(accIF[0], aIF, b00, b01);
            MMAT(accGO[0], aGO, b00, b01);
            MMAT(accIF[1], aIF, b10, b11);
            MMAT(accGO[1], aGO, b10, b11);
        }
    };
    xw_compute(0);

    for (int t = 0; t < TI; ++t) {
        const int p = t & 1;
        // ---- h-GEMM: acc += W_hh * h(t-1) from hbuf[p] ----
        const uint32_t* hbuf = (const uint32_t*)(smem + SM_H + p * HB);
#pragma unroll
        for (int kc = 0; kc < 8; ++kc) {
            uint32_t b00 = hbuf[hb0 + kc * 8], b01 = hbuf[hb0 + kc * 8 + 4];
            uint32_t b10 = hbuf[hb1 + kc * 8], b11 = hbuf[hb1 + kc * 8 + 4];
            MMAT(accIF[0], whhIF[kc], b00, b01);
            MMAT(accGO[0], whhGO[kc], b00, b01);
            MMAT(accIF[1], whhIF[kc], b10, b11);
            MMAT(accGO[1], whhGO[kc], b10, b11);
        }

        // ---- in-register activations; h(t) -> hbuf[1-p] as tf32 fp32 ----
        uint32_t* hw = (uint32_t*)(smem + SM_H + (1 - p) * HB);
#pragma unroll
        for (int j = 0; j < 2; ++j)
#pragma unroll
            for (int e = 0; e < 2; ++e) {
                float ig = sigmap(accIF[j][e]);
                float fg = sigmap(accIF[j][2 + e]);
                float gg = tanhap(accGO[j][e]);
                float og = sigmap(accGO[j][2 + e]);
                float cv = fmaf(fg, c[j * 2 + e], ig * gg);
                c[j * 2 + e] = cv;
                float hv = og * tanhap(cv);
                const int cb = j * 8 + 2 * tig + e;   // batch row
                hw[cb * WKS + u] = tf32_(hv);
                if (t == TI - 1)
                    ((float*)(smem + SM_HS))[cb * HH + u] = hv;
            }
        // ---- stage x(t+2) from regs; refill with x(t+3) ----
        if (stager && t + 2 < TI) {
            uint4 q = make_uint4(tf32_(xreg.x), tf32_(xreg.y),
                                 tf32_(xreg.z), tf32_(xreg.w));
            *(uint4*)(smem + SM_X + p * XB + (srow * XKS + sseg * 4) * 4) = q;
            if (t + 3 < TI)
                xreg = *reinterpret_cast<const float4*>(
                    x + ((size_t)(b0 + srow) * TI + (t + 3)) * II + sseg * 4);
        }
        // ---- acc = bias + xw(t+1) (off h-path) ----
        if (t + 1 < TI) xw_compute((t + 1) & 1);

        __syncthreads();   // publishes h(t) + x(t+2)
    }

    // ---- final linear: out = h_T @ W_out^T + b_out ----
    float* scr = (float*)(smem + SM_SCR);
    for (int idx = tid; idx < OUTD * HH; idx += NTHR) scr[idx] = W_out[idx];
    if (tid < OUTD) scr[OUTD * HH + tid] = b_out[tid];
    __syncthreads();

    const float* Hs = (const float*)(smem + SM_HS);
    for (int cell = tid; cell < MB * OUTD; cell += NTHR) {
        int row = cell / OUTD;
        int o   = cell - row * OUTD;
        float s = scr[OUTD * HH + o];
#pragma unroll
        for (int j = 0; j < HH; ++j)
            s = fmaf(Hs[row * HH + j], scr[o * HH + j], s);
        out[(size_t)(b0 + row) * OUTD + o] = s;
    }
}

extern "C" void kernel_launch(void* const* d_in, const int* in_sizes, int n_in,
                              void* d_out, int out_size)
{
    const float* x     = (const float*)d_in[0];
    const float* W_ih  = (const float*)d_in[1];
    const float* W_hh  = (const float*)d_in[2];
    const float* b_ih  = (const float*)d_in[3];
    const float* b_hh  = (const float*)d_in[4];
    const float* W_out = (const float*)d_in[5];
    const float* b_out = (const float*)d_in[6];
    float* outp = (float*)d_out;

    cudaFuncSetAttribute(lstm_kernel,
                         cudaFuncAttributeMaxDynamicSharedMemorySize, SMEM_BYTES);
    lstm_kernel<<<BB / MB, NTHR, SMEM_BYTES>>>(x, W_ih, W_hh, b_ih, b_hh,
                                               W_out, b_out, outp);
}